// round 10
// baseline (speedup 1.0000x reference)
#include <cuda_runtime.h>

// Problem shapes (fixed by the reference)
#define MDIM 16384
#define NDIM 16384
#define BC   8          // B * C_IN = 2*4
#define CHUNK 1024      // m-chunk staged in shared: 8 * 1024 * 4B = 32 KB
#define ROWS_PER_BLOCK 32
#define THREADS 256

// y[b,o,n] = sum_c theta[o,c] * (sum_m D[n,m] x[b,c,m]) + bias[o]
// Strategy: accumulate X over the 8 (b,c) channels per row while streaming D
// once (HBM-bound), fold theta/bias in the epilogue.
__global__ __launch_bounds__(THREADS, 2)
void coboundary_kernel(const float* __restrict__ D,
                       const float* __restrict__ x,      // [8][MDIM]
                       const float* __restrict__ theta,  // [8][4]
                       const float* __restrict__ bias,   // [8]
                       float* __restrict__ out)          // [16][NDIM]
{
    __shared__ float sx[BC][CHUNK];

    const int tid = threadIdx.x;
    const int tx  = tid & 31;        // lane
    const int ty  = tid >> 5;        // warp 0..7
    const int row0 = blockIdx.x * ROWS_PER_BLOCK + ty * 4;

    float acc[4][BC];
#pragma unroll
    for (int r = 0; r < 4; ++r)
#pragma unroll
        for (int c = 0; c < BC; ++c) acc[r][c] = 0.0f;

    for (int chunk = 0; chunk < MDIM; chunk += CHUNK) {
        __syncthreads();   // protect sx from previous iteration's readers
        // Cooperative stage of the x chunk: each thread copies one float4 per channel.
#pragma unroll
        for (int bc = 0; bc < BC; ++bc) {
            const float4* src =
                reinterpret_cast<const float4*>(x + (size_t)bc * MDIM + chunk);
            reinterpret_cast<float4*>(&sx[bc][0])[tid] = src[tid];
        }
        __syncthreads();

#pragma unroll 2
        for (int i = 0; i < CHUNK / 128; ++i) {
            const int mo = i * 128 + tx * 4;

            // 8 conflict-free LDS.128 (lanes read consecutive 16B)
            float4 xs[BC];
#pragma unroll
            for (int bc = 0; bc < BC; ++bc)
                xs[bc] = *reinterpret_cast<const float4*>(&sx[bc][mo]);

            // Batch the 4 row loads up front (MLP=4 per thread, coalesced)
            float4 d[4];
#pragma unroll
            for (int r = 0; r < 4; ++r)
                d[r] = *reinterpret_cast<const float4*>(
                    &D[(size_t)(row0 + r) * MDIM + chunk + mo]);

#pragma unroll
            for (int r = 0; r < 4; ++r) {
#pragma unroll
                for (int bc = 0; bc < BC; ++bc) {
                    acc[r][bc] = fmaf(d[r].x, xs[bc].x, acc[r][bc]);
                    acc[r][bc] = fmaf(d[r].y, xs[bc].y, acc[r][bc]);
                    acc[r][bc] = fmaf(d[r].z, xs[bc].z, acc[r][bc]);
                    acc[r][bc] = fmaf(d[r].w, xs[bc].w, acc[r][bc]);
                }
            }
        }
    }

    // Butterfly reduction: every lane ends with the full row sums.
#pragma unroll
    for (int r = 0; r < 4; ++r)
#pragma unroll
        for (int c = 0; c < BC; ++c)
#pragma unroll
            for (int off = 16; off > 0; off >>= 1)
                acc[r][c] += __shfl_xor_sync(0xffffffffu, acc[r][c], off);

    // Epilogue: fold theta + bias. Warp owns 4 rows * 16 (b,o) = 64 outputs;
    // each lane writes 2.
    const int r = tx >> 3;        // 0..3
    const int k = tx & 7;         // 0..7
    const int n = row0 + r;
#pragma unroll
    for (int t = 0; t < 2; ++t) {
        const int bo = k + t * 8;     // 0..15
        const int b  = bo >> 3;
        const int o  = bo & 7;
        const float4 th = *reinterpret_cast<const float4*>(&theta[o * 4]);
        float y = bias[o];
        y = fmaf(th.x, acc[r][b * 4 + 0], y);
        y = fmaf(th.y, acc[r][b * 4 + 1], y);
        y = fmaf(th.z, acc[r][b * 4 + 2], y);
        y = fmaf(th.w, acc[r][b * 4 + 3], y);
        out[(size_t)bo * NDIM + n] = y;
    }
}

extern "C" void kernel_launch(void* const* d_in, const int* in_sizes, int n_in,
                              void* d_out, int out_size)
{
    const float* D     = (const float*)d_in[0];   // [16384,16384]
    const float* x     = (const float*)d_in[1];   // [2,4,16384]
    const float* theta = (const float*)d_in[2];   // [8,4]
    const float* bias  = (const float*)d_in[3];   // [1,8,1] -> 8 floats
    float* out = (float*)d_out;                   // [2,8,16384]

    const int blocks = NDIM / ROWS_PER_BLOCK;     // 512
    coboundary_kernel<<<blocks, THREADS>>>(D, x, theta, bias, out);
}

// round 11
// speedup vs baseline: 1.1420x; 1.1420x over previous
#include <cuda_runtime.h>

// Problem shapes (fixed by the reference)
#define MDIM 16384
#define NDIM 16384
#define BC   8          // B * C_IN = 2*4
#define CHUNK 512       // m-chunk staged in shared: 8 * 512 * 4B = 16 KB
#define ROWS_PER_BLOCK 16
#define THREADS 128     // 4 warps; each warp owns 4 rows

// y[b,o,n] = sum_c theta[o,c] * (sum_m D[n,m] x[b,c,m]) + bias[o]
// Single-wave launch: 1024 blocks = 7 per SM on 148 SMs, all resident.
__global__ __launch_bounds__(THREADS, 7)
void coboundary_kernel(const float* __restrict__ D,
                       const float* __restrict__ x,      // [8][MDIM]
                       const float* __restrict__ theta,  // [8][4]
                       const float* __restrict__ bias,   // [8]
                       float* __restrict__ out)          // [16][NDIM]
{
    __shared__ float sx[BC][CHUNK];

    const int tid = threadIdx.x;
    const int tx  = tid & 31;        // lane
    const int ty  = tid >> 5;        // warp 0..3
    const int row0 = blockIdx.x * ROWS_PER_BLOCK + ty * 4;

    float acc[4][BC];
#pragma unroll
    for (int r = 0; r < 4; ++r)
#pragma unroll
        for (int c = 0; c < BC; ++c) acc[r][c] = 0.0f;

    const float4* __restrict__ x4 = reinterpret_cast<const float4*>(x);

    for (int chunk = 0; chunk < MDIM; chunk += CHUNK) {
        __syncthreads();   // protect sx from previous iteration's readers
        // Stage the x chunk: 128 float4 per channel -> one per thread.
#pragma unroll
        for (int bc = 0; bc < BC; ++bc) {
            reinterpret_cast<float4*>(&sx[bc][0])[tid] =
                x4[(size_t)bc * (MDIM / 4) + (chunk >> 2) + tid];
        }
        __syncthreads();

#pragma unroll
        for (int i = 0; i < CHUNK / 128; ++i) {
            const int mo = i * 128 + tx * 4;
            const float* dbase = D + (size_t)row0 * MDIM + chunk + mo;

            // Batch the 4 row loads up front (MLP=4/thread, coalesced,
            // streaming hint: D has zero reuse).
            float4 d[4];
#pragma unroll
            for (int r = 0; r < 4; ++r)
                d[r] = __ldcs(reinterpret_cast<const float4*>(
                    dbase + (size_t)r * MDIM));

            // Interleave channels so only one xs float4 is live at a time
            // (keeps regs under the 7-blocks/SM budget).
#pragma unroll
            for (int bc = 0; bc < BC; ++bc) {
                const float4 xs = *reinterpret_cast<const float4*>(&sx[bc][mo]);
#pragma unroll
                for (int r = 0; r < 4; ++r) {
                    acc[r][bc] = fmaf(d[r].x, xs.x, acc[r][bc]);
                    acc[r][bc] = fmaf(d[r].y, xs.y, acc[r][bc]);
                    acc[r][bc] = fmaf(d[r].z, xs.z, acc[r][bc]);
                    acc[r][bc] = fmaf(d[r].w, xs.w, acc[r][bc]);
                }
            }
        }
    }

    // Butterfly reduction: every lane ends with the full row sums.
#pragma unroll
    for (int r = 0; r < 4; ++r)
#pragma unroll
        for (int c = 0; c < BC; ++c)
#pragma unroll
            for (int off = 16; off > 0; off >>= 1)
                acc[r][c] += __shfl_xor_sync(0xffffffffu, acc[r][c], off);

    // Epilogue: fold theta + bias. Warp owns 4 rows * 16 (b,o) = 64 outputs;
    // each lane writes 2.
    const int r = tx >> 3;        // 0..3
    const int k = tx & 7;         // 0..7
    const int n = row0 + r;
#pragma unroll
    for (int t = 0; t < 2; ++t) {
        const int bo = k + t * 8;     // 0..15
        const int b  = bo >> 3;
        const int o  = bo & 7;
        const float4 th = *reinterpret_cast<const float4*>(&theta[o * 4]);
        float y = bias[o];
        y = fmaf(th.x, acc[r][b * 4 + 0], y);
        y = fmaf(th.y, acc[r][b * 4 + 1], y);
        y = fmaf(th.z, acc[r][b * 4 + 2], y);
        y = fmaf(th.w, acc[r][b * 4 + 3], y);
        out[(size_t)bo * NDIM + n] = y;
    }
}

extern "C" void kernel_launch(void* const* d_in, const int* in_sizes, int n_in,
                              void* d_out, int out_size)
{
    const float* D     = (const float*)d_in[0];   // [16384,16384]
    const float* x     = (const float*)d_in[1];   // [2,4,16384]
    const float* theta = (const float*)d_in[2];   // [8,4]
    const float* bias  = (const float*)d_in[3];   // [1,8,1] -> 8 floats
    float* out = (float*)d_out;                   // [2,8,16384]

    const int blocks = NDIM / ROWS_PER_BLOCK;     // 1024 = single wave @ 7/SM
    coboundary_kernel<<<blocks, THREADS>>>(D, x, theta, bias, out);
}

// round 12
// speedup vs baseline: 1.1556x; 1.0119x over previous
#include <cuda_runtime.h>

// Problem shapes (fixed by the reference)
#define MDIM 16384
#define NDIM 16384
#define BC   8          // B * C_IN = 2*4
#define CHUNK 512       // m-chunk staged in shared: 8 * 512 * 4B = 16 KB
#define ROWS_PER_BLOCK 16
#define THREADS 128     // 4 warps; each warp owns 4 rows

// y[b,o,n] = sum_c theta[o,c] * (sum_m D[n,m] x[b,c,m]) + bias[o]
// Single-wave launch: 1024 blocks = 7 per SM on 148 SMs, all resident.
__global__ __launch_bounds__(THREADS, 7)
void coboundary_kernel(const float* __restrict__ D,
                       const float* __restrict__ x,      // [8][MDIM]
                       const float* __restrict__ theta,  // [8][4]
                       const float* __restrict__ bias,   // [8]
                       float* __restrict__ out)          // [16][NDIM]
{
    __shared__ float sx[BC][CHUNK];

    const int tid = threadIdx.x;
    const int tx  = tid & 31;        // lane
    const int ty  = tid >> 5;        // warp 0..3
    const int row0 = blockIdx.x * ROWS_PER_BLOCK + ty * 4;

    float acc[4][BC];
#pragma unroll
    for (int r = 0; r < 4; ++r)
#pragma unroll
        for (int c = 0; c < BC; ++c) acc[r][c] = 0.0f;

    const float4* __restrict__ x4 = reinterpret_cast<const float4*>(x);

    for (int chunk = 0; chunk < MDIM; chunk += CHUNK) {
        __syncthreads();   // protect sx from previous iteration's readers
        // Stage the x chunk: 128 float4 per channel -> one per thread.
#pragma unroll
        for (int bc = 0; bc < BC; ++bc) {
            reinterpret_cast<float4*>(&sx[bc][0])[tid] =
                x4[(size_t)bc * (MDIM / 4) + (chunk >> 2) + tid];
        }
        __syncthreads();

#pragma unroll
        for (int i = 0; i < CHUNK / 128; ++i) {
            const int mo = i * 128 + tx * 4;
            const float* dbase = D + (size_t)row0 * MDIM + chunk + mo;

            // Batch the 4 row loads up front (MLP=4/thread, coalesced,
            // streaming hint: D has zero reuse).
            float4 d[4];
#pragma unroll
            for (int r = 0; r < 4; ++r)
                d[r] = __ldcs(reinterpret_cast<const float4*>(
                    dbase + (size_t)r * MDIM));

            // Interleave channels so only one xs float4 is live at a time
            // (keeps regs under the 7-blocks/SM budget).
#pragma unroll
            for (int bc = 0; bc < BC; ++bc) {
                const float4 xs = *reinterpret_cast<const float4*>(&sx[bc][mo]);
#pragma unroll
                for (int r = 0; r < 4; ++r) {
                    acc[r][bc] = fmaf(d[r].x, xs.x, acc[r][bc]);
                    acc[r][bc] = fmaf(d[r].y, xs.y, acc[r][bc]);
                    acc[r][bc] = fmaf(d[r].z, xs.z, acc[r][bc]);
                    acc[r][bc] = fmaf(d[r].w, xs.w, acc[r][bc]);
                }
            }
        }
    }

    // Butterfly reduction: every lane ends with the full row sums.
#pragma unroll
    for (int r = 0; r < 4; ++r)
#pragma unroll
        for (int c = 0; c < BC; ++c)
#pragma unroll
            for (int off = 16; off > 0; off >>= 1)
                acc[r][c] += __shfl_xor_sync(0xffffffffu, acc[r][c], off);

    // Epilogue: fold theta + bias. Warp owns 4 rows * 16 (b,o) = 64 outputs;
    // each lane writes 2.
    const int r = tx >> 3;        // 0..3
    const int k = tx & 7;         // 0..7
    const int n = row0 + r;
#pragma unroll
    for (int t = 0; t < 2; ++t) {
        const int bo = k + t * 8;     // 0..15
        const int b  = bo >> 3;
        const int o  = bo & 7;
        const float4 th = *reinterpret_cast<const float4*>(&theta[o * 4]);
        float y = bias[o];
        y = fmaf(th.x, acc[r][b * 4 + 0], y);
        y = fmaf(th.y, acc[r][b * 4 + 1], y);
        y = fmaf(th.z, acc[r][b * 4 + 2], y);
        y = fmaf(th.w, acc[r][b * 4 + 3], y);
        out[(size_t)bo * NDIM + n] = y;
    }
}

extern "C" void kernel_launch(void* const* d_in, const int* in_sizes, int n_in,
                              void* d_out, int out_size)
{
    const float* D     = (const float*)d_in[0];   // [16384,16384]
    const float* x     = (const float*)d_in[1];   // [2,4,16384]
    const float* theta = (const float*)d_in[2];   // [8,4]
    const float* bias  = (const float*)d_in[3];   // [1,8,1] -> 8 floats
    float* out = (float*)d_out;                   // [2,8,16384]

    const int blocks = NDIM / ROWS_PER_BLOCK;     // 1024 = single wave @ 7/SM
    coboundary_kernel<<<blocks, THREADS>>>(D, x, theta, bias, out);
}